// round 11
// baseline (speedup 1.0000x reference)
#include <cuda_runtime.h>
#include <cstdint>

// CompressK: mean-pool over sliding windows of 32 rows, stride 16.
// k: (BATCH*SEQ_LEN, 4, 128) fp32 -> row = 512 floats = 128 float4
// out: (4092, 4, 128) fp32 followed by cu_comp (BATCH+1) as fp32 values.
//
// Block-sum sharing: chunk c = (S_c + S_{c+1})/32, S_j = 16-row block sum.
// CH=16 -> 17 block-sums per segment -> 1.0625x minimal read (144 MiB).
//
// Barrier-free design: 256 threads = 8 warps; lane pairs (l, l+16) own
// float4 column w*16+(l&15), each sums 8 of the 16 rows (8 independent
// LDG.128 per thread per block-sum), combined with 4x shfl_xor(16).
// No __syncthreads anywhere -> loads batch freely across block-sums.

#define BATCH 4
#define SEQ_LEN 16384
#define ROW_FLOATS 512
#define ROW_F4 128
#define CHUNKS_PER_BATCH 1023     // (16384-32)/16 + 1
#define TOTAL_CHUNKS (BATCH * CHUNKS_PER_BATCH)   // 4092
#define CH 16
#define SEGS_PER_BATCH ((CHUNKS_PER_BATCH + CH - 1) / CH)    // 64
#define OUT_FLOATS ((size_t)TOTAL_CHUNKS * ROW_FLOATS)       // 2,095,104
#define NTHREADS 256

__global__ __launch_bounds__(NTHREADS) void compress_k_kernel(
    const float4* __restrict__ k4, float4* __restrict__ out4,
    float* __restrict__ out_scalar)
{
    const int tid  = threadIdx.x;           // 0..255
    const int w    = tid >> 5;              // warp 0..7
    const int lane = tid & 31;
    const int half = lane >> 4;             // 0: rows 0-7, 1: rows 8-15
    const int li   = lane & 15;
    const int c    = w * 16 + li;           // float4 column 0..127

    const int batch = blockIdx.x / SEGS_PER_BATCH;
    const int seg   = blockIdx.x % SEGS_PER_BATCH;

    // Fused cu_comp tail (fp32 values; exact for these magnitudes)
    if (blockIdx.x == 0 && tid <= BATCH) {
        out_scalar[OUT_FLOATS + tid] = (float)(tid * CHUNKS_PER_BATCH);
    }

    const int c_begin = seg * CH;
    int nch = CHUNKS_PER_BATCH - c_begin;
    if (nch > CH) nch = CH;

    const size_t base_row = (size_t)batch * SEQ_LEN + (size_t)c_begin * 16;
    // this thread's first row within each 16-row block-sum: half*8
    const float4* src = k4 + (base_row + (size_t)half * 8) * ROW_F4 + c;

    const float inv32 = 1.0f / 32.0f;
    float4 sPrev = make_float4(0.f, 0.f, 0.f, 0.f);

    const size_t out_base = ((size_t)batch * CHUNKS_PER_BATCH + c_begin) * ROW_F4 + c;

    for (int j = 0; j <= nch; ++j) {
        // 8 independent LDG.128 (rows j*16 + half*8 + 0..7)
        const float4* p = src + (size_t)j * 16 * ROW_F4;
        float4 v0 = p[0 * ROW_F4];
        float4 v1 = p[1 * ROW_F4];
        float4 v2 = p[2 * ROW_F4];
        float4 v3 = p[3 * ROW_F4];
        float4 v4 = p[4 * ROW_F4];
        float4 v5 = p[5 * ROW_F4];
        float4 v6 = p[6 * ROW_F4];
        float4 v7 = p[7 * ROW_F4];

        float4 s;
        s.x = ((v0.x + v1.x) + (v2.x + v3.x)) + ((v4.x + v5.x) + (v6.x + v7.x));
        s.y = ((v0.y + v1.y) + (v2.y + v3.y)) + ((v4.y + v5.y) + (v6.y + v7.y));
        s.z = ((v0.z + v1.z) + (v2.z + v3.z)) + ((v4.z + v5.z) + (v6.z + v7.z));
        s.w = ((v0.w + v1.w) + (v2.w + v3.w)) + ((v4.w + v5.w) + (v6.w + v7.w));

        // combine the two row-halves: lanes l and l^16 own the same column
        s.x += __shfl_xor_sync(0xffffffffu, s.x, 16);
        s.y += __shfl_xor_sync(0xffffffffu, s.y, 16);
        s.z += __shfl_xor_sync(0xffffffffu, s.z, 16);
        s.w += __shfl_xor_sync(0xffffffffu, s.w, 16);

        if (j > 0 && half == 0) {
            float4 o;
            o.x = (sPrev.x + s.x) * inv32;
            o.y = (sPrev.y + s.y) * inv32;
            o.z = (sPrev.z + s.z) * inv32;
            o.w = (sPrev.w + s.w) * inv32;
            out4[out_base + (size_t)(j - 1) * ROW_F4] = o;
        }
        sPrev = s;
    }
}

extern "C" void kernel_launch(void* const* d_in, const int* in_sizes, int n_in,
                              void* d_out, int out_size)
{
    const float4* k4 = (const float4*)d_in[0];

    dim3 grid(BATCH * SEGS_PER_BATCH);   // 256
    compress_k_kernel<<<grid, NTHREADS>>>(k4, (float4*)d_out, (float*)d_out);
}

// round 12
// speedup vs baseline: 1.1808x; 1.1808x over previous
#include <cuda_runtime.h>
#include <cstdint>

// CompressK: mean-pool over sliding windows of 32 rows, stride 16.
// k: (BATCH*SEQ_LEN, 4, 128) fp32 -> row = 512 floats = 128 float4
// out: (4092, 4, 128) fp32 followed by cu_comp (BATCH+1) as fp32 values.
//
// R5 geometry (best measured: 5.79 TB/s) with MLP deepened 4 -> 8:
// CH=8, full-row blocks, grid 512. 256 threads = 2 row-halves x 128 f4
// columns; each thread sums 8 consecutive rows per 16-row block-sum
// (8 independent LDG.128 back-to-back), partials combined via a
// double-buffered smem stage (no shfl, no cross-barrier prefetch).

#define BATCH 4
#define SEQ_LEN 16384
#define ROW_FLOATS 512
#define ROW_F4 128
#define CHUNKS_PER_BATCH 1023     // (16384-32)/16 + 1
#define TOTAL_CHUNKS (BATCH * CHUNKS_PER_BATCH)   // 4092
#define CH 8
#define SEGS_PER_BATCH ((CHUNKS_PER_BATCH + CH - 1) / CH)    // 128
#define OUT_FLOATS ((size_t)TOTAL_CHUNKS * ROW_FLOATS)       // 2,095,104
#define NTHREADS 256

__global__ __launch_bounds__(NTHREADS) void compress_k_kernel(
    const float4* __restrict__ k4, float* __restrict__ out)
{
    __shared__ float4 part[2][2][ROW_F4];   // [buf][row-half][f4 col] = 8 KB

    const int tid  = threadIdx.x;           // 0..255
    const int col4 = tid & 127;             // float4 column
    const int h    = tid >> 7;              // row half 0..1 (8 rows each)

    const int batch = blockIdx.x / SEGS_PER_BATCH;
    const int seg   = blockIdx.x % SEGS_PER_BATCH;

    // Fused cu_comp tail (fp32 values; exact for these magnitudes)
    if (blockIdx.x == 0 && tid <= BATCH) {
        out[OUT_FLOATS + tid] = (float)(tid * CHUNKS_PER_BATCH);
    }

    const int c_begin = seg * CH;
    int nch = CHUNKS_PER_BATCH - c_begin;
    if (nch > CH) nch = CH;

    const size_t base_row = (size_t)batch * SEQ_LEN + (size_t)c_begin * 16;
    // this thread's first row within each 16-row block-sum: h*8
    const float4* src = k4 + (base_row + (size_t)h * 8) * ROW_F4 + col4;

    const float* partf = (const float*)part;   // scalar view

    const float inv32 = 1.0f / 32.0f;
    float sPrev0 = 0.0f, sPrev1 = 0.0f;        // two scalar columns/thread
    int buf = 0;

    const size_t out_base = ((size_t)batch * CHUNKS_PER_BATCH + c_begin) * ROW_FLOATS;

    for (int j = 0; j <= nch; ++j) {
        // 8 independent LDG.128 (rows j*16 + h*8 + 0..7)
        const float4* p = src + (size_t)j * 16 * ROW_F4;
        float4 v0 = p[0 * ROW_F4];
        float4 v1 = p[1 * ROW_F4];
        float4 v2 = p[2 * ROW_F4];
        float4 v3 = p[3 * ROW_F4];
        float4 v4 = p[4 * ROW_F4];
        float4 v5 = p[5 * ROW_F4];
        float4 v6 = p[6 * ROW_F4];
        float4 v7 = p[7 * ROW_F4];

        float4 ps;
        ps.x = ((v0.x + v1.x) + (v2.x + v3.x)) + ((v4.x + v5.x) + (v6.x + v7.x));
        ps.y = ((v0.y + v1.y) + (v2.y + v3.y)) + ((v4.y + v5.y) + (v6.y + v7.y));
        ps.z = ((v0.z + v1.z) + (v2.z + v3.z)) + ((v4.z + v5.z) + (v6.z + v7.z));
        ps.w = ((v0.w + v1.w) + (v2.w + v3.w)) + ((v4.w + v5.w) + (v6.w + v7.w));
        part[buf][h][col4] = ps;

        __syncthreads();

        // combine: thread owns scalar columns tid and tid+256
        const float* pb = partf + (size_t)buf * 2 * ROW_FLOATS;
        float s0 = pb[tid]             + pb[ROW_FLOATS + tid];
        float s1 = pb[tid + NTHREADS]  + pb[ROW_FLOATS + tid + NTHREADS];

        if (j > 0) {
            float* o = out + out_base + (size_t)(j - 1) * ROW_FLOATS;
            o[tid]            = (sPrev0 + s0) * inv32;
            o[tid + NTHREADS] = (sPrev1 + s1) * inv32;
        }
        sPrev0 = s0;
        sPrev1 = s1;
        buf ^= 1;
    }
}

extern "C" void kernel_launch(void* const* d_in, const int* in_sizes, int n_in,
                              void* d_out, int out_size)
{
    const float4* k4 = (const float4*)d_in[0];

    dim3 grid(BATCH * SEGS_PER_BATCH);   // 512
    compress_k_kernel<<<grid, NTHREADS>>>(k4, (float*)d_out);
}

// round 13
// speedup vs baseline: 1.3185x; 1.1166x over previous
#include <cuda_runtime.h>
#include <cstdint>

// CompressK: mean-pool over sliding windows of 32 rows, stride 16.
// k: (BATCH*SEQ_LEN, 4, 128) fp32 -> row = 512 floats = 128 float4
// out: (4092, 4, 128) fp32 followed by cu_comp (BATCH+1) as fp32 values.
//
// R5 parameters (best measured: 5.79 TB/s): CH=8, full-row blocks,
// 512 threads, grid 512 (8192 warps), double-buffered smem combine.
// NEW: TWO block-sums per barrier interval -> 5 barriers/block (was 9).
// 512 threads = 4 groups (2 block-sums x 2 row-halves) x 128 f4 cols;
// each thread issues 8 independent LDG.128 per interval.

#define BATCH 4
#define SEQ_LEN 16384
#define ROW_FLOATS 512
#define ROW_F4 128
#define CHUNKS_PER_BATCH 1023     // (16384-32)/16 + 1
#define TOTAL_CHUNKS (BATCH * CHUNKS_PER_BATCH)   // 4092
#define CH 8
#define SEGS_PER_BATCH ((CHUNKS_PER_BATCH + CH - 1) / CH)    // 128
#define OUT_FLOATS ((size_t)TOTAL_CHUNKS * ROW_FLOATS)       // 2,095,104
#define NTHREADS 512

__global__ __launch_bounds__(NTHREADS) void compress_k_kernel(
    const float4* __restrict__ k4, float* __restrict__ out)
{
    __shared__ float4 part[2][4][ROW_F4];   // [buf][group][f4 col] = 16 KB

    const int tid  = threadIdx.x;           // 0..511
    const int col4 = tid & 127;             // float4 column
    const int g    = tid >> 7;              // group 0..3
    const int b    = g >> 1;                // which block-sum of the pair
    const int h    = g & 1;                 // row half (8 rows each)

    const int batch = blockIdx.x / SEGS_PER_BATCH;
    const int seg   = blockIdx.x % SEGS_PER_BATCH;

    // Fused cu_comp tail (fp32 values; exact for these magnitudes)
    if (blockIdx.x == 0 && tid <= BATCH) {
        out[OUT_FLOATS + tid] = (float)(tid * CHUNKS_PER_BATCH);
    }

    const int c_begin = seg * CH;
    int nch = CHUNKS_PER_BATCH - c_begin;
    if (nch > CH) nch = CH;                  // 8, or 7 on the last segment

    const size_t base_row = (size_t)batch * SEQ_LEN + (size_t)c_begin * 16;
    const float4* base = k4 + base_row * ROW_F4 + col4;

    const float* partf = (const float*)part;   // scalar view
    const float inv32 = 1.0f / 32.0f;

    const size_t out_base = ((size_t)batch * CHUNKS_PER_BATCH + c_begin) * ROW_FLOATS + tid;

    // ---- prologue: block-sum S_0 (quarter-split, MLP-4) ----
    float sPrev;
    {
        const float4* p = base + (size_t)g * 4 * ROW_F4;  // rows g*4..g*4+3
        float4 v0 = p[0 * ROW_F4];
        float4 v1 = p[1 * ROW_F4];
        float4 v2 = p[2 * ROW_F4];
        float4 v3 = p[3 * ROW_F4];
        float4 ps;
        ps.x = (v0.x + v1.x) + (v2.x + v3.x);
        ps.y = (v0.y + v1.y) + (v2.y + v3.y);
        ps.z = (v0.z + v1.z) + (v2.z + v3.z);
        ps.w = (v0.w + v1.w) + (v2.w + v3.w);
        part[0][g][col4] = ps;
        __syncthreads();
        sPrev = (partf[0 * ROW_FLOATS + tid] + partf[1 * ROW_FLOATS + tid])
              + (partf[2 * ROW_FLOATS + tid] + partf[3 * ROW_FLOATS + tid]);
    }

    // ---- main loop: block-sums S_t, S_{t+1} per barrier interval ----
    int buf = 1;
    for (int t = 1; t <= nch; t += 2) {
        const bool has2 = (t + 1 <= nch);
        // this thread's block-sum index: t + b; rows (t+b)*16 + h*8 + 0..7
        if (b == 0 || has2) {
            const float4* p = base + ((size_t)(t + b) * 16 + (size_t)h * 8) * ROW_F4;
            float4 v0 = p[0 * ROW_F4];
            float4 v1 = p[1 * ROW_F4];
            float4 v2 = p[2 * ROW_F4];
            float4 v3 = p[3 * ROW_F4];
            float4 v4 = p[4 * ROW_F4];
            float4 v5 = p[5 * ROW_F4];
            float4 v6 = p[6 * ROW_F4];
            float4 v7 = p[7 * ROW_F4];
            float4 ps;
            ps.x = ((v0.x + v1.x) + (v2.x + v3.x)) + ((v4.x + v5.x) + (v6.x + v7.x));
            ps.y = ((v0.y + v1.y) + (v2.y + v3.y)) + ((v4.y + v5.y) + (v6.y + v7.y));
            ps.z = ((v0.z + v1.z) + (v2.z + v3.z)) + ((v4.z + v5.z) + (v6.z + v7.z));
            ps.w = ((v0.w + v1.w) + (v2.w + v3.w)) + ((v4.w + v5.w) + (v6.w + v7.w));
            part[buf][g][col4] = ps;
        }

        __syncthreads();

        const float* pb = partf + (size_t)buf * 4 * ROW_FLOATS;
        float s1 = pb[0 * ROW_FLOATS + tid] + pb[1 * ROW_FLOATS + tid];

        // chunk t-1 = (S_{t-1} + S_t) / 32
        out[out_base + (size_t)(t - 1) * ROW_FLOATS] = (sPrev + s1) * inv32;

        if (has2) {
            float s2 = pb[2 * ROW_FLOATS + tid] + pb[3 * ROW_FLOATS + tid];
            // chunk t = (S_t + S_{t+1}) / 32
            out[out_base + (size_t)t * ROW_FLOATS] = (s1 + s2) * inv32;
            sPrev = s2;
        } else {
            sPrev = s1;
        }
        buf ^= 1;
    }
}

extern "C" void kernel_launch(void* const* d_in, const int* in_sizes, int n_in,
                              void* d_out, int out_size)
{
    const float4* k4 = (const float4*)d_in[0];

    dim3 grid(BATCH * SEGS_PER_BATCH);   // 512
    compress_k_kernel<<<grid, NTHREADS>>>(k4, (float*)d_out);
}